// round 3
// baseline (speedup 1.0000x reference)
#include <cuda_runtime.h>
#include <math.h>

#define LEN 17821
#define DMODEL 384
#define HNUM 8
#define DH 48

// ---------------- scratch (device globals; no allocation) ----------------
__device__ float g_q[LEN * DMODEL];
__device__ float g_value[LEN * DMODEL];
__device__ float g_off[LEN * 256];
__device__ float g_attn[LEN * 128];
__device__ float g_msda[LEN * DMODEL];
__device__ float g_src2[LEN * DMODEL];
__device__ float g_xyln[LEN * 256];
__device__ float g_zdln[LEN * 128];
__device__ float g_hxy[LEN * 256];
__device__ float g_hzd[LEN * 128];
__device__ float g_xy2[LEN * 256];
__device__ float g_zd2[LEN * 128];

// ---------------- q = src + pos ----------------
__global__ void add_kernel(const float4* __restrict__ a, const float4* __restrict__ b,
                           float4* __restrict__ o, int n4) {
    int i = blockIdx.x * blockDim.x + threadIdx.x;
    if (i < n4) {
        float4 x = a[i], y = b[i];
        o[i] = make_float4(x.x + y.x, x.y + y.y, x.z + y.z, x.w + y.w);
    }
}

// ---------------- tiled SGEMM: Y[M,N] = X[M,K] @ W[N,K]^T + bias, optional relu ----------------
__global__ __launch_bounds__(256)
void sgemm_nt(const float* __restrict__ X, const float* __restrict__ W,
              const float* __restrict__ bias, float* __restrict__ Y,
              int M, int N, int K, int relu)
{
    __shared__ float Xs[16][64];
    __shared__ float Ws[16][64];
    int tid = threadIdx.x;
    int tx = tid & 15, ty = tid >> 4;
    int m0 = blockIdx.y * 64, n0 = blockIdx.x * 64;
    int lrow = tid >> 2;
    int lcol = (tid & 3) << 2;

    float acc[4][4];
#pragma unroll
    for (int i = 0; i < 4; i++)
#pragma unroll
        for (int j = 0; j < 4; j++) acc[i][j] = 0.f;

    for (int k0 = 0; k0 < K; k0 += 16) {
        float4 xv = make_float4(0.f, 0.f, 0.f, 0.f);
        int m = m0 + lrow;
        if (m < M) xv = *reinterpret_cast<const float4*>(X + (size_t)m * K + k0 + lcol);
        Xs[lcol + 0][lrow] = xv.x; Xs[lcol + 1][lrow] = xv.y;
        Xs[lcol + 2][lrow] = xv.z; Xs[lcol + 3][lrow] = xv.w;

        float4 wv = *reinterpret_cast<const float4*>(W + (size_t)(n0 + lrow) * K + k0 + lcol);
        Ws[lcol + 0][lrow] = wv.x; Ws[lcol + 1][lrow] = wv.y;
        Ws[lcol + 2][lrow] = wv.z; Ws[lcol + 3][lrow] = wv.w;
        __syncthreads();

#pragma unroll
        for (int k = 0; k < 16; k++) {
            float4 a = *reinterpret_cast<const float4*>(&Xs[k][ty << 2]);
            float4 b = *reinterpret_cast<const float4*>(&Ws[k][tx << 2]);
            float av[4] = {a.x, a.y, a.z, a.w};
            float bv[4] = {b.x, b.y, b.z, b.w};
#pragma unroll
            for (int i = 0; i < 4; i++)
#pragma unroll
                for (int j = 0; j < 4; j++)
                    acc[i][j] = fmaf(av[i], bv[j], acc[i][j]);
        }
        __syncthreads();
    }

#pragma unroll
    for (int i = 0; i < 4; i++) {
        int m = m0 + (ty << 2) + i;
        if (m >= M) continue;
#pragma unroll
        for (int j = 0; j < 4; j++) {
            int n = n0 + (tx << 2) + j;
            float v = acc[i][j] + bias[n];
            if (relu) v = fmaxf(v, 0.f);
            Y[(size_t)m * N + n] = v;
        }
    }
}

// ---------------- softmax over groups of 16 (contiguous) ----------------
__global__ void softmax16_kernel(float* __restrict__ a, int ngroups) {
    int g = blockIdx.x * blockDim.x + threadIdx.x;
    if (g >= ngroups) return;
    float* p = a + (size_t)g * 16;
    float v[16], mx = -1e30f;
#pragma unroll
    for (int i = 0; i < 16; i++) { v[i] = p[i]; mx = fmaxf(mx, v[i]); }
    float s = 0.f;
#pragma unroll
    for (int i = 0; i < 16; i++) { v[i] = expf(v[i] - mx); s += v[i]; }
    float inv = 1.f / s;
#pragma unroll
    for (int i = 0; i < 16; i++) p[i] = v[i] * inv;
}

// ---------------- multi-scale deformable attention core ----------------
// block = 96 threads: 8 heads x 12 lanes, each lane owns 4 channels (float4)
__global__ __launch_bounds__(96)
void msda_kernel(const float* __restrict__ value, const float* __restrict__ off,
                 const float* __restrict__ attn, const float* __restrict__ ref,
                 float* __restrict__ out)
{
    const int HlA[4] = {100, 50, 25, 13};
    const int WlA[4] = {134, 67, 34, 17};
    const int stA[4] = {0, 13400, 16750, 17600};

    int q = blockIdx.x;
    int tid = threadIdx.x;
    int head = tid / 12;
    int lane = tid % 12;
    int c0 = lane * 4;

    __shared__ float s_off[256];
    __shared__ float s_attn[128];
    __shared__ float s_ref[8];
    for (int i = tid; i < 256; i += 96) s_off[i] = off[(size_t)q * 256 + i];
    for (int i = tid; i < 128; i += 96) s_attn[i] = attn[(size_t)q * 128 + i];
    if (tid < 8) s_ref[tid] = ref[(size_t)q * 8 + tid];
    __syncthreads();

    float acc0 = 0.f, acc1 = 0.f, acc2 = 0.f, acc3 = 0.f;

#pragma unroll
    for (int l = 0; l < 4; l++) {
        const int Wli = WlA[l], Hli = HlA[l];
        const float fw = (float)Wli, fh = (float)Hli;
        const float rx = s_ref[l * 2 + 0], ry = s_ref[l * 2 + 1];
        const float* vb = value + (size_t)stA[l] * DMODEL + head * DH + c0;
#pragma unroll
        for (int p = 0; p < 4; p++) {
            int base = (head * 4 + l) * 4 + p;
            float ox = s_off[base * 2 + 0], oy = s_off[base * 2 + 1];
            float a = s_attn[base];
            float locx = rx + ox / fw;
            float locy = ry + oy / fh;
            float x = locx * fw - 0.5f;
            float y = locy * fh - 0.5f;
            float x0f = floorf(x), y0f = floorf(y);
            float dx = x - x0f, dy = y - y0f;
            int x0 = (int)x0f, y0 = (int)y0f;
            float w00 = (1.f - dx) * (1.f - dy) * a;
            float w10 = dx * (1.f - dy) * a;
            float w01 = (1.f - dx) * dy * a;
            float w11 = dx * dy * a;
#pragma unroll
            for (int cy = 0; cy < 2; cy++) {
                int yi = y0 + cy;
                if (yi < 0 || yi >= Hli) continue;
#pragma unroll
                for (int cx = 0; cx < 2; cx++) {
                    int xi = x0 + cx;
                    if (xi < 0 || xi >= Wli) continue;
                    float w = cy ? (cx ? w11 : w01) : (cx ? w10 : w00);
                    float4 g = *reinterpret_cast<const float4*>(vb + (size_t)(yi * Wli + xi) * DMODEL);
                    acc0 = fmaf(g.x, w, acc0);
                    acc1 = fmaf(g.y, w, acc1);
                    acc2 = fmaf(g.z, w, acc2);
                    acc3 = fmaf(g.w, w, acc3);
                }
            }
        }
    }
    *reinterpret_cast<float4*>(out + (size_t)q * DMODEL + head * DH + c0) =
        make_float4(acc0, acc1, acc2, acc3);
}

// ---------------- block reduction of 4 values (128 threads) ----------------
__device__ __forceinline__ void block_reduce4(float& a, float& b, float& c, float& d,
                                              float* sbuf) {
    unsigned mask = 0xffffffffu;
#pragma unroll
    for (int o = 16; o > 0; o >>= 1) {
        a += __shfl_down_sync(mask, a, o);
        b += __shfl_down_sync(mask, b, o);
        c += __shfl_down_sync(mask, c, o);
        d += __shfl_down_sync(mask, d, o);
    }
    int warp = threadIdx.x >> 5, lanei = threadIdx.x & 31;
    if (lanei == 0) {
        sbuf[warp * 4 + 0] = a; sbuf[warp * 4 + 1] = b;
        sbuf[warp * 4 + 2] = c; sbuf[warp * 4 + 3] = d;
    }
    __syncthreads();
    if (threadIdx.x == 0) {
        float ta = 0, tb = 0, tc = 0, td = 0;
        for (int w = 0; w < 4; w++) {
            ta += sbuf[w * 4 + 0]; tb += sbuf[w * 4 + 1];
            tc += sbuf[w * 4 + 2]; td += sbuf[w * 4 + 3];
        }
        sbuf[0] = ta; sbuf[1] = tb; sbuf[2] = tc; sbuf[3] = td;
    }
    __syncthreads();
    a = sbuf[0]; b = sbuf[1]; c = sbuf[2]; d = sbuf[3];
}

// ---------------- LN after attention: splits 256 / 128 ----------------
__global__ __launch_bounds__(128)
void ln1_kernel(const float* __restrict__ src, const float* __restrict__ src2,
                const float* __restrict__ gxy, const float* __restrict__ bxy,
                const float* __restrict__ gzd, const float* __restrict__ bzd,
                float* __restrict__ xy, float* __restrict__ zd)
{
    __shared__ float sbuf[16];
    int q = blockIdx.x, t = threadIdx.x;
    size_t base = (size_t)q * DMODEL;
    float v0 = src[base + t]       + src2[base + t];
    float v1 = src[base + 128 + t] + src2[base + 128 + t];
    float v2 = src[base + 256 + t] + src2[base + 256 + t];
    float sxy = v0 + v1, sqxy = v0 * v0 + v1 * v1, szd = v2, sqzd = v2 * v2;
    block_reduce4(sxy, sqxy, szd, sqzd, sbuf);
    float mxy = sxy * (1.f / 256.f);
    float rxy = rsqrtf(sqxy * (1.f / 256.f) - mxy * mxy + 1e-5f);
    float mzd = szd * (1.f / 128.f);
    float rzd = rsqrtf(sqzd * (1.f / 128.f) - mzd * mzd + 1e-5f);
    xy[(size_t)q * 256 + t]       = (v0 - mxy) * rxy * gxy[t]       + bxy[t];
    xy[(size_t)q * 256 + 128 + t] = (v1 - mxy) * rxy * gxy[128 + t] + bxy[128 + t];
    zd[(size_t)q * 128 + t]       = (v2 - mzd) * rzd * gzd[t]       + bzd[t];
}

// ---------------- final residual + LN, write output ----------------
__global__ __launch_bounds__(128)
void ln2_kernel(const float* __restrict__ xyln, const float* __restrict__ xy2,
                const float* __restrict__ zdln, const float* __restrict__ zd2,
                const float* __restrict__ gxy, const float* __restrict__ bxy,
                const float* __restrict__ gzd, const float* __restrict__ bzd,
                float* __restrict__ out)
{
    __shared__ float sbuf[16];
    int q = blockIdx.x, t = threadIdx.x;
    float v0 = xyln[(size_t)q * 256 + t]       + xy2[(size_t)q * 256 + t];
    float v1 = xyln[(size_t)q * 256 + 128 + t] + xy2[(size_t)q * 256 + 128 + t];
    float v2 = zdln[(size_t)q * 128 + t]       + zd2[(size_t)q * 128 + t];
    float sxy = v0 + v1, sqxy = v0 * v0 + v1 * v1, szd = v2, sqzd = v2 * v2;
    block_reduce4(sxy, sqxy, szd, sqzd, sbuf);
    float mxy = sxy * (1.f / 256.f);
    float rxy = rsqrtf(sqxy * (1.f / 256.f) - mxy * mxy + 1e-5f);
    float mzd = szd * (1.f / 128.f);
    float rzd = rsqrtf(sqzd * (1.f / 128.f) - mzd * mzd + 1e-5f);
    size_t ob = (size_t)q * DMODEL;
    out[ob + t]       = (v0 - mxy) * rxy * gxy[t]       + bxy[t];
    out[ob + 128 + t] = (v1 - mxy) * rxy * gxy[128 + t] + bxy[128 + t];
    out[ob + 256 + t] = (v2 - mzd) * rzd * gzd[t]       + bzd[t];
}

// ---------------- host launch ----------------
extern "C" void kernel_launch(void* const* d_in, const int* in_sizes, int n_in,
                              void* d_out, int out_size) {
    const float* src    = (const float*)d_in[0];
    const float* pos    = (const float*)d_in[3];
    const float* ref    = (const float*)d_in[4];
    const float* W_off  = (const float*)d_in[8];
    const float* b_off  = (const float*)d_in[9];
    const float* W_attn = (const float*)d_in[10];
    const float* b_attn = (const float*)d_in[11];
    const float* W_val  = (const float*)d_in[12];
    const float* b_val  = (const float*)d_in[13];
    const float* W_out  = (const float*)d_in[14];
    const float* b_out  = (const float*)d_in[15];
    const float* g1xy   = (const float*)d_in[16];
    const float* b1xy   = (const float*)d_in[17];
    const float* g1zd   = (const float*)d_in[18];
    const float* b1zd   = (const float*)d_in[19];
    const float* fxy_w1 = (const float*)d_in[20];
    const float* fxy_b1 = (const float*)d_in[21];
    const float* fxy_w2 = (const float*)d_in[22];
    const float* fxy_b2 = (const float*)d_in[23];
    const float* fxy_g  = (const float*)d_in[24];
    const float* fxy_b  = (const float*)d_in[25];
    const float* fzd_w1 = (const float*)d_in[26];
    const float* fzd_b1 = (const float*)d_in[27];
    const float* fzd_w2 = (const float*)d_in[28];
    const float* fzd_b2 = (const float*)d_in[29];
    const float* fzd_g  = (const float*)d_in[30];
    const float* fzd_b  = (const float*)d_in[31];
    float* out = (float*)d_out;

    float *q, *value, *off, *attn, *msda, *src2, *xyln, *zdln, *hxy, *hzd, *xy2, *zd2;
    cudaGetSymbolAddress((void**)&q, g_q);
    cudaGetSymbolAddress((void**)&value, g_value);
    cudaGetSymbolAddress((void**)&off, g_off);
    cudaGetSymbolAddress((void**)&attn, g_attn);
    cudaGetSymbolAddress((void**)&msda, g_msda);
    cudaGetSymbolAddress((void**)&src2, g_src2);
    cudaGetSymbolAddress((void**)&xyln, g_xyln);
    cudaGetSymbolAddress((void**)&zdln, g_zdln);
    cudaGetSymbolAddress((void**)&hxy, g_hxy);
    cudaGetSymbolAddress((void**)&hzd, g_hzd);
    cudaGetSymbolAddress((void**)&xy2, g_xy2);
    cudaGetSymbolAddress((void**)&zd2, g_zd2);

    int n4 = LEN * DMODEL / 4;
    add_kernel<<<(n4 + 255) / 256, 256>>>((const float4*)src, (const float4*)pos,
                                          (float4*)q, n4);

    int mt = (LEN + 63) / 64;
    sgemm_nt<<<dim3(384 / 64, mt), 256>>>(src, W_val, b_val, value, LEN, 384, 384, 0);
    sgemm_nt<<<dim3(256 / 64, mt), 256>>>(q, W_off, b_off, off, LEN, 256, 384, 0);
    sgemm_nt<<<dim3(128 / 64, mt), 256>>>(q, W_attn, b_attn, attn, LEN, 128, 384, 0);

    softmax16_kernel<<<(LEN * 8 + 255) / 256, 256>>>(attn, LEN * 8);

    msda_kernel<<<LEN, 96>>>(value, off, attn, ref, msda);

    sgemm_nt<<<dim3(384 / 64, mt), 256>>>(msda, W_out, b_out, src2, LEN, 384, 384, 0);

    ln1_kernel<<<LEN, 128>>>(src, src2, g1xy, b1xy, g1zd, b1zd, xyln, zdln);

    sgemm_nt<<<dim3(256 / 64, mt), 256>>>(xyln, fxy_w1, fxy_b1, hxy, LEN, 256, 256, 1);
    sgemm_nt<<<dim3(256 / 64, mt), 256>>>(hxy, fxy_w2, fxy_b2, xy2, LEN, 256, 256, 0);
    sgemm_nt<<<dim3(128 / 64, mt), 256>>>(zdln, fzd_w1, fzd_b1, hzd, LEN, 128, 128, 1);
    sgemm_nt<<<dim3(128 / 64, mt), 256>>>(hzd, fzd_w2, fzd_b2, zd2, LEN, 128, 128, 0);

    ln2_kernel<<<LEN, 128>>>(xyln, xy2, zdln, zd2, fxy_g, fxy_b, fzd_g, fzd_b, out);
}

// round 4
// speedup vs baseline: 2.3103x; 2.3103x over previous
#include <cuda_runtime.h>
#include <cstdint>
#include <math.h>

#define LEN 17821
#define DMODEL 384
#define HNUM 8
#define DH 48

// ---------------- scratch (device globals; no allocation) ----------------
__device__ float g_q[LEN * DMODEL];
__device__ float g_value[LEN * DMODEL];
__device__ float g_off[LEN * 256];
__device__ float g_attn[LEN * 128];
__device__ float g_msda[LEN * DMODEL];
__device__ float g_src2[LEN * DMODEL];
__device__ float g_xyln[LEN * 256];
__device__ float g_zdln[LEN * 128];
__device__ float g_hxy[LEN * 256];
__device__ float g_hzd[LEN * 128];
__device__ float g_xy2[LEN * 256];
__device__ float g_zd2[LEN * 128];

// ---------------- q = src + pos ----------------
__global__ void add_kernel(const float4* __restrict__ a, const float4* __restrict__ b,
                           float4* __restrict__ o, int n4) {
    int i = blockIdx.x * blockDim.x + threadIdx.x;
    if (i < n4) {
        float4 x = a[i], y = b[i];
        o[i] = make_float4(x.x + y.x, x.y + y.y, x.z + y.z, x.w + y.w);
    }
}

// ================= TF32 tensor-core GEMM =================
// Y[M,N] = X[M,K] @ W[N,K]^T + bias, optional relu.
// CTA tile 128x64, 8 warps (4x2), warp tile 32x32, BK=16, cp.async double buffer.
#define BM 128
#define BN 64
#define BK 16
#define AST 20   // padded smem row stride (floats): (20*m + k) % 32 distinct per warp

__device__ __forceinline__ void cp_async16(void* smem_dst, const void* gmem_src, bool pred) {
    uint32_t dst = (uint32_t)__cvta_generic_to_shared(smem_dst);
    int sz = pred ? 16 : 0;
    asm volatile("cp.async.cg.shared.global [%0], [%1], 16, %2;\n"
                 :: "r"(dst), "l"(gmem_src), "r"(sz));
}

__global__ __launch_bounds__(256)
void tf32_gemm(const float* __restrict__ X, const float* __restrict__ W,
               const float* __restrict__ bias, float* __restrict__ Y,
               int M, int N, int K, int relu)
{
    __shared__ __align__(16) float As[2][BM * AST];
    __shared__ __align__(16) float Bs[2][BN * AST];

    const int tid = threadIdx.x;
    const int m0 = blockIdx.y * BM;
    const int n0 = blockIdx.x * BN;
    const int lane = tid & 31, w = tid >> 5;
    const int grp = lane >> 2, tig = lane & 3;
    const int wm0 = (w >> 1) * 32, wn0 = (w & 1) * 32;

    // cp.async mapping: A has 128 rows x 4 quads (512), B has 64 rows x 4 quads (256)
    const int arow = tid >> 2;          // 0..63 (and arow+64)
    const int aq   = (tid & 3) * 4;     // float offset of quad
    const bool av0 = (m0 + arow) < M;
    const bool av1 = (m0 + arow + 64) < M;
    const int ar0 = av0 ? (m0 + arow) : (M - 1);
    const int ar1 = av1 ? (m0 + arow + 64) : (M - 1);
    const int br  = n0 + arow;          // 0..63 rows of W tile, N multiple of 64

    float acc[2][4][4];
#pragma unroll
    for (int mi = 0; mi < 2; mi++)
#pragma unroll
        for (int ni = 0; ni < 4; ni++)
#pragma unroll
            for (int i = 0; i < 4; i++) acc[mi][ni][i] = 0.f;

    const int KT = K / BK;

    // prologue: stage 0
    {
        cp_async16(&As[0][arow * AST + aq],        X + (size_t)ar0 * K + aq, av0);
        cp_async16(&As[0][(arow + 64) * AST + aq], X + (size_t)ar1 * K + aq, av1);
        cp_async16(&Bs[0][arow * AST + aq],        W + (size_t)br * K + aq, true);
        asm volatile("cp.async.commit_group;\n");
    }

    for (int kt = 0; kt < KT; kt++) {
        if (kt + 1 < KT) {
            int buf = (kt + 1) & 1;
            int k0 = (kt + 1) * BK;
            cp_async16(&As[buf][arow * AST + aq],        X + (size_t)ar0 * K + k0 + aq, av0);
            cp_async16(&As[buf][(arow + 64) * AST + aq], X + (size_t)ar1 * K + k0 + aq, av1);
            cp_async16(&Bs[buf][arow * AST + aq],        W + (size_t)br * K + k0 + aq, true);
            asm volatile("cp.async.commit_group;\n");
            asm volatile("cp.async.wait_group 1;\n");
        } else {
            asm volatile("cp.async.wait_group 0;\n");
        }
        __syncthreads();

        const float* Ab = As[kt & 1];
        const float* Bb = Bs[kt & 1];
#pragma unroll
        for (int ks = 0; ks < 2; ks++) {
            const int kk = ks * 8;
            uint32_t a[2][4], b[4][2];
#pragma unroll
            for (int mi = 0; mi < 2; mi++) {
                int m = wm0 + mi * 16 + grp;
                a[mi][0] = __float_as_uint(Ab[m * AST + kk + tig]);
                a[mi][1] = __float_as_uint(Ab[(m + 8) * AST + kk + tig]);
                a[mi][2] = __float_as_uint(Ab[m * AST + kk + tig + 4]);
                a[mi][3] = __float_as_uint(Ab[(m + 8) * AST + kk + tig + 4]);
            }
#pragma unroll
            for (int ni = 0; ni < 4; ni++) {
                int n = wn0 + ni * 8 + grp;
                b[ni][0] = __float_as_uint(Bb[n * AST + kk + tig]);
                b[ni][1] = __float_as_uint(Bb[n * AST + kk + tig + 4]);
            }
#pragma unroll
            for (int mi = 0; mi < 2; mi++)
#pragma unroll
                for (int ni = 0; ni < 4; ni++)
                    asm volatile(
                        "mma.sync.aligned.m16n8k8.row.col.f32.tf32.tf32.f32 "
                        "{%0,%1,%2,%3}, {%4,%5,%6,%7}, {%8,%9}, {%0,%1,%2,%3};\n"
                        : "+f"(acc[mi][ni][0]), "+f"(acc[mi][ni][1]),
                          "+f"(acc[mi][ni][2]), "+f"(acc[mi][ni][3])
                        : "r"(a[mi][0]), "r"(a[mi][1]), "r"(a[mi][2]), "r"(a[mi][3]),
                          "r"(b[ni][0]), "r"(b[ni][1]));
        }
        __syncthreads();
    }

    // epilogue
#pragma unroll
    for (int mi = 0; mi < 2; mi++) {
#pragma unroll
        for (int i = 0; i < 2; i++) {
            int m = m0 + wm0 + mi * 16 + grp + i * 8;
            if (m >= M) continue;
#pragma unroll
            for (int ni = 0; ni < 4; ni++) {
                int n = n0 + wn0 + ni * 8 + tig * 2;
                float v0 = acc[mi][ni][i * 2 + 0] + bias[n];
                float v1 = acc[mi][ni][i * 2 + 1] + bias[n + 1];
                if (relu) { v0 = fmaxf(v0, 0.f); v1 = fmaxf(v1, 0.f); }
                *reinterpret_cast<float2*>(Y + (size_t)m * N + n) = make_float2(v0, v1);
            }
        }
    }
}

// ---------------- softmax over groups of 16 (contiguous) ----------------
__global__ void softmax16_kernel(float* __restrict__ a, int ngroups) {
    int g = blockIdx.x * blockDim.x + threadIdx.x;
    if (g >= ngroups) return;
    float* p = a + (size_t)g * 16;
    float v[16], mx = -1e30f;
#pragma unroll
    for (int i = 0; i < 16; i++) { v[i] = p[i]; mx = fmaxf(mx, v[i]); }
    float s = 0.f;
#pragma unroll
    for (int i = 0; i < 16; i++) { v[i] = expf(v[i] - mx); s += v[i]; }
    float inv = 1.f / s;
#pragma unroll
    for (int i = 0; i < 16; i++) p[i] = v[i] * inv;
}

// ---------------- multi-scale deformable attention core ----------------
// block = 96 threads: 8 heads x 12 lanes, each lane owns 4 channels (float4)
__global__ __launch_bounds__(96)
void msda_kernel(const float* __restrict__ value, const float* __restrict__ off,
                 const float* __restrict__ attn, const float* __restrict__ ref,
                 float* __restrict__ out)
{
    const int HlA[4] = {100, 50, 25, 13};
    const int WlA[4] = {134, 67, 34, 17};
    const int stA[4] = {0, 13400, 16750, 17600};

    int q = blockIdx.x;
    int tid = threadIdx.x;
    int head = tid / 12;
    int lane = tid % 12;
    int c0 = lane * 4;

    __shared__ float s_off[256];
    __shared__ float s_attn[128];
    __shared__ float s_ref[8];
    for (int i = tid; i < 256; i += 96) s_off[i] = off[(size_t)q * 256 + i];
    for (int i = tid; i < 128; i += 96) s_attn[i] = attn[(size_t)q * 128 + i];
    if (tid < 8) s_ref[tid] = ref[(size_t)q * 8 + tid];
    __syncthreads();

    float acc0 = 0.f, acc1 = 0.f, acc2 = 0.f, acc3 = 0.f;

#pragma unroll
    for (int l = 0; l < 4; l++) {
        const int Wli = WlA[l], Hli = HlA[l];
        const float fw = (float)Wli, fh = (float)Hli;
        const float rx = s_ref[l * 2 + 0], ry = s_ref[l * 2 + 1];
        const float* vb = value + (size_t)stA[l] * DMODEL + head * DH + c0;
#pragma unroll
        for (int p = 0; p < 4; p++) {
            int base = (head * 4 + l) * 4 + p;
            float ox = s_off[base * 2 + 0], oy = s_off[base * 2 + 1];
            float a = s_attn[base];
            float locx = rx + ox / fw;
            float locy = ry + oy / fh;
            float x = locx * fw - 0.5f;
            float y = locy * fh - 0.5f;
            float x0f = floorf(x), y0f = floorf(y);
            float dx = x - x0f, dy = y - y0f;
            int x0 = (int)x0f, y0 = (int)y0f;
            float w00 = (1.f - dx) * (1.f - dy) * a;
            float w10 = dx * (1.f - dy) * a;
            float w01 = (1.f - dx) * dy * a;
            float w11 = dx * dy * a;
#pragma unroll
            for (int cy = 0; cy < 2; cy++) {
                int yi = y0 + cy;
                if (yi < 0 || yi >= Hli) continue;
#pragma unroll
                for (int cx = 0; cx < 2; cx++) {
                    int xi = x0 + cx;
                    if (xi < 0 || xi >= Wli) continue;
                    float wgt = cy ? (cx ? w11 : w01) : (cx ? w10 : w00);
                    float4 g = *reinterpret_cast<const float4*>(vb + (size_t)(yi * Wli + xi) * DMODEL);
                    acc0 = fmaf(g.x, wgt, acc0);
                    acc1 = fmaf(g.y, wgt, acc1);
                    acc2 = fmaf(g.z, wgt, acc2);
                    acc3 = fmaf(g.w, wgt, acc3);
                }
            }
        }
    }
    *reinterpret_cast<float4*>(out + (size_t)q * DMODEL + head * DH + c0) =
        make_float4(acc0, acc1, acc2, acc3);
}

// ---------------- block reduction of 4 values (128 threads) ----------------
__device__ __forceinline__ void block_reduce4(float& a, float& b, float& c, float& d,
                                              float* sbuf) {
    unsigned mask = 0xffffffffu;
#pragma unroll
    for (int o = 16; o > 0; o >>= 1) {
        a += __shfl_down_sync(mask, a, o);
        b += __shfl_down_sync(mask, b, o);
        c += __shfl_down_sync(mask, c, o);
        d += __shfl_down_sync(mask, d, o);
    }
    int warp = threadIdx.x >> 5, lanei = threadIdx.x & 31;
    if (lanei == 0) {
        sbuf[warp * 4 + 0] = a; sbuf[warp * 4 + 1] = b;
        sbuf[warp * 4 + 2] = c; sbuf[warp * 4 + 3] = d;
    }
    __syncthreads();
    if (threadIdx.x == 0) {
        float ta = 0, tb = 0, tc = 0, td = 0;
        for (int w = 0; w < 4; w++) {
            ta += sbuf[w * 4 + 0]; tb += sbuf[w * 4 + 1];
            tc += sbuf[w * 4 + 2]; td += sbuf[w * 4 + 3];
        }
        sbuf[0] = ta; sbuf[1] = tb; sbuf[2] = tc; sbuf[3] = td;
    }
    __syncthreads();
    a = sbuf[0]; b = sbuf[1]; c = sbuf[2]; d = sbuf[3];
}

// ---------------- LN after attention: splits 256 / 128 ----------------
__global__ __launch_bounds__(128)
void ln1_kernel(const float* __restrict__ src, const float* __restrict__ src2,
                const float* __restrict__ gxy, const float* __restrict__ bxy,
                const float* __restrict__ gzd, const float* __restrict__ bzd,
                float* __restrict__ xy, float* __restrict__ zd)
{
    __shared__ float sbuf[16];
    int q = blockIdx.x, t = threadIdx.x;
    size_t base = (size_t)q * DMODEL;
    float v0 = src[base + t]       + src2[base + t];
    float v1 = src[base + 128 + t] + src2[base + 128 + t];
    float v2 = src[base + 256 + t] + src2[base + 256 + t];
    float sxy = v0 + v1, sqxy = v0 * v0 + v1 * v1, szd = v2, sqzd = v2 * v2;
    block_reduce4(sxy, sqxy, szd, sqzd, sbuf);
    float mxy = sxy * (1.f / 256.f);
    float rxy = rsqrtf(sqxy * (1.f / 256.f) - mxy * mxy + 1e-5f);
    float mzd = szd * (1.f / 128.f);
    float rzd = rsqrtf(sqzd * (1.f / 128.f) - mzd * mzd + 1e-5f);
    xy[(size_t)q * 256 + t]       = (v0 - mxy) * rxy * gxy[t]       + bxy[t];
    xy[(size_t)q * 256 + 128 + t] = (v1 - mxy) * rxy * gxy[128 + t] + bxy[128 + t];
    zd[(size_t)q * 128 + t]       = (v2 - mzd) * rzd * gzd[t]       + bzd[t];
}

// ---------------- final residual + LN, write output ----------------
__global__ __launch_bounds__(128)
void ln2_kernel(const float* __restrict__ xyln, const float* __restrict__ xy2,
                const float* __restrict__ zdln, const float* __restrict__ zd2,
                const float* __restrict__ gxy, const float* __restrict__ bxy,
                const float* __restrict__ gzd, const float* __restrict__ bzd,
                float* __restrict__ out)
{
    __shared__ float sbuf[16];
    int q = blockIdx.x, t = threadIdx.x;
    float v0 = xyln[(size_t)q * 256 + t]       + xy2[(size_t)q * 256 + t];
    float v1 = xyln[(size_t)q * 256 + 128 + t] + xy2[(size_t)q * 256 + 128 + t];
    float v2 = zdln[(size_t)q * 128 + t]       + zd2[(size_t)q * 128 + t];
    float sxy = v0 + v1, sqxy = v0 * v0 + v1 * v1, szd = v2, sqzd = v2 * v2;
    block_reduce4(sxy, sqxy, szd, sqzd, sbuf);
    float mxy = sxy * (1.f / 256.f);
    float rxy = rsqrtf(sqxy * (1.f / 256.f) - mxy * mxy + 1e-5f);
    float mzd = szd * (1.f / 128.f);
    float rzd = rsqrtf(sqzd * (1.f / 128.f) - mzd * mzd + 1e-5f);
    size_t ob = (size_t)q * DMODEL;
    out[ob + t]       = (v0 - mxy) * rxy * gxy[t]       + bxy[t];
    out[ob + 128 + t] = (v1 - mxy) * rxy * gxy[128 + t] + bxy[128 + t];
    out[ob + 256 + t] = (v2 - mzd) * rzd * gzd[t]       + bzd[t];
}

// ---------------- host launch ----------------
extern "C" void kernel_launch(void* const* d_in, const int* in_sizes, int n_in,
                              void* d_out, int out_size) {
    const float* src    = (const float*)d_in[0];
    const float* pos    = (const float*)d_in[3];
    const float* ref    = (const float*)d_in[4];
    const float* W_off  = (const float*)d_in[8];
    const float* b_off  = (const float*)d_in[9];
    const float* W_attn = (const float*)d_in[10];
    const float* b_attn = (const float*)d_in[11];
    const float* W_val  = (const float*)d_in[12];
    const float* b_val  = (const float*)d_in[13];
    const float* W_out  = (const float*)d_in[14];
    const float* b_out  = (const float*)d_in[15];
    const float* g1xy   = (const float*)d_in[16];
    const float* b1xy   = (const float*)d_in[17];
    const float* g1zd   = (const float*)d_in[18];
    const float* b1zd   = (const float*)d_in[19];
    const float* fxy_w1 = (const float*)d_in[20];
    const float* fxy_b1 = (const float*)d_in[21];
    const float* fxy_w2 = (const float*)d_in[22];
    const float* fxy_b2 = (const float*)d_in[23];
    const float* fxy_g  = (const float*)d_in[24];
    const float* fxy_b  = (const float*)d_in[25];
    const float* fzd_w1 = (const float*)d_in[26];
    const float* fzd_b1 = (const float*)d_in[27];
    const float* fzd_w2 = (const float*)d_in[28];
    const float* fzd_b2 = (const float*)d_in[29];
    const float* fzd_g  = (const float*)d_in[30];
    const float* fzd_b  = (const float*)d_in[31];
    float* out = (float*)d_out;

    float *q, *value, *off, *attn, *msda, *src2, *xyln, *zdln, *hxy, *hzd, *xy2, *zd2;
    cudaGetSymbolAddress((void**)&q, g_q);
    cudaGetSymbolAddress((void**)&value, g_value);
    cudaGetSymbolAddress((void**)&off, g_off);
    cudaGetSymbolAddress((void**)&attn, g_attn);
    cudaGetSymbolAddress((void**)&msda, g_msda);
    cudaGetSymbolAddress((void**)&src2, g_src2);
    cudaGetSymbolAddress((void**)&xyln, g_xyln);
    cudaGetSymbolAddress((void**)&zdln, g_zdln);
    cudaGetSymbolAddress((void**)&hxy, g_hxy);
    cudaGetSymbolAddress((void**)&hzd, g_hzd);
    cudaGetSymbolAddress((void**)&xy2, g_xy2);
    cudaGetSymbolAddress((void**)&zd2, g_zd2);

    int n4 = LEN * DMODEL / 4;
    add_kernel<<<(n4 + 255) / 256, 256>>>((const float4*)src, (const float4*)pos,
                                          (float4*)q, n4);

    int mt = (LEN + BM - 1) / BM;   // 140
    tf32_gemm<<<dim3(384 / BN, mt), 256>>>(src, W_val, b_val, value, LEN, 384, 384, 0);
    tf32_gemm<<<dim3(256 / BN, mt), 256>>>(q, W_off, b_off, off, LEN, 256, 384, 0);
    tf32_gemm<<<dim3(128 / BN, mt), 256>>>(q, W_attn, b_attn, attn, LEN, 128, 384, 0);

    softmax16_kernel<<<(LEN * 8 + 255) / 256, 256>>>(attn, LEN * 8);

    msda_kernel<<<LEN, 96>>>(value, off, attn, ref, msda);

    tf32_gemm<<<dim3(384 / BN, mt), 256>>>(msda, W_out, b_out, src2, LEN, 384, 384, 0);

    ln1_kernel<<<LEN, 128>>>(src, src2, g1xy, b1xy, g1zd, b1zd, xyln, zdln);

    tf32_gemm<<<dim3(256 / BN, mt), 256>>>(xyln, fxy_w1, fxy_b1, hxy, LEN, 256, 256, 1);
    tf32_gemm<<<dim3(256 / BN, mt), 256>>>(hxy, fxy_w2, fxy_b2, xy2, LEN, 256, 256, 0);
    tf32_gemm<<<dim3(128 / BN, mt), 256>>>(zdln, fzd_w1, fzd_b1, hzd, LEN, 128, 128, 1);
    tf32_gemm<<<dim3(128 / BN, mt), 256>>>(hzd, fzd_w2, fzd_b2, zd2, LEN, 128, 128, 0);

    ln2_kernel<<<LEN, 128>>>(xyln, xy2, zdln, zd2, fxy_g, fxy_b, fzd_g, fzd_b, out);
}